// round 3
// baseline (speedup 1.0000x reference)
#include <cuda_runtime.h>

#define NT 100000
#define NC 100000
#define NE 1600000
#define NP 200000
#define HD 128

#define GRID 148
#define TPB  512
#define NTH  (GRID * TPB)

// ---- scratch (static __device__, zero-initialized at load; re-zeroed each call) ----
__device__ float  g_dis_t[NT];
__device__ float  g_dis_c[NC];
__device__ float  g_coef[NT];
__device__ float4 g_gc4[NC];
__device__ float4 g_xd4[NC];
__device__ float4 g_u[NT + NC];

// ---- grid barrier state (self-resetting) ----
__device__ unsigned g_count;
__device__ unsigned g_release;
__device__ unsigned g_exit;

__device__ __forceinline__ void grid_bar(unsigned phase) {
    __syncthreads();
    if (threadIdx.x == 0) {
        __threadfence();
        unsigned prev = atomicAdd(&g_count, 1u);
        if (prev == GRID - 1) {
            atomicExch(&g_count, 0u);
            __threadfence();
            atomicExch(&g_release, phase);
        } else {
            while (atomicAdd(&g_release, 0u) < phase) __nanosleep(64);
        }
        __threadfence();
    }
    __syncthreads();
}

__device__ __forceinline__ void red_add_v4(float4* addr, float a, float b, float c, float d) {
    asm volatile("red.global.add.v4.f32 [%0], {%1,%2,%3,%4};"
                 :: "l"(addr), "f"(a), "f"(b), "f"(c), "f"(d) : "memory");
}

__global__ void __launch_bounds__(TPB)
fused_kernel(const float* __restrict__ xcar,
             const int* __restrict__ eit,
             const int* __restrict__ eic,
             const float* __restrict__ ew,
             const int* __restrict__ src,
             const int* __restrict__ dst,
             const float* __restrict__ Wt, const float* __restrict__ bt,
             const float* __restrict__ Wc, const float* __restrict__ bc,
             const float* __restrict__ wl, const float* __restrict__ bl,
             float* __restrict__ out) {
    const int tid = blockIdx.x * TPB + threadIdx.x;

    // ---- per-block M = B diag(wl) B^T  (6x6), kept in smem for phase E ----
    __shared__ float sB[6][HD];
    __shared__ float sBw[HD];
    __shared__ float sM[36];
    {
        int h = threadIdx.x;
        if (h < HD) {
            sB[0][h] = Wt[h];
            sB[1][h] = bt[h];
            sB[2][h] = Wc[h];
            sB[3][h] = Wc[HD + h];
            sB[4][h] = Wc[2 * HD + h];
            sB[5][h] = bc[h];
            sBw[h] = wl[h];
        }
        __syncthreads();
        int warp = threadIdx.x >> 5, lane = threadIdx.x & 31;
        if (warp < 4) {
            for (int pi = warp; pi < 36; pi += 4) {
                int i = pi / 6, j = pi % 6;
                float s = 0.f;
                #pragma unroll
                for (int t = lane; t < HD; t += 32)
                    s += sB[i][t] * sB[j][t] * sBw[t];
                #pragma unroll
                for (int o = 16; o > 0; o >>= 1)
                    s += __shfl_xor_sync(0xffffffff, s, o);
                if (lane == 0) sM[pi] = s;
            }
        }
    }

    // ---- phase A: degree accumulation (4 edges/iter) ----
    for (int q = tid; q < NE / 4; q += NTH) {
        int base = q * 4;
        int4   ct4 = *(const int4*)(eit + NE + base);
        int4   cc4 = *(const int4*)(eic + NE + base);
        float4 w4  = *(const float4*)(ew + base);
        atomicAdd(&g_dis_t[ct4.x], 1.0f);
        atomicAdd(&g_dis_t[ct4.y], 1.0f);
        atomicAdd(&g_dis_t[ct4.z], 1.0f);
        atomicAdd(&g_dis_t[ct4.w], 1.0f);
        atomicAdd(&g_dis_c[cc4.x], w4.x);
        atomicAdd(&g_dis_c[cc4.y], w4.y);
        atomicAdd(&g_dis_c[cc4.z], w4.z);
        atomicAdd(&g_dis_c[cc4.w], w4.w);
    }
    grid_bar(1);

    // ---- phase B: deg -> dis; pack (x0,x1,x2,dis_c) ----
    for (int i = tid; i < NC; i += NTH) {
        g_dis_t[i] = rsqrtf(g_dis_t[i] + 1.0f);
        float d = rsqrtf(g_dis_c[i] + 1.0f);
        g_dis_c[i] = d;
        g_xd4[i] = make_float4(xcar[3 * i + 0], xcar[3 * i + 1], xcar[3 * i + 2], d);
    }
    grid_bar(2);

    // ---- phase C: edge aggregation (edge arrays L2-hot from phase A) ----
    for (int q = tid; q < NE / 4; q += NTH) {
        int base = q * 4;
        int4   rt4 = *(const int4*)(eit + base);
        int4   ct4 = *(const int4*)(eit + NE + base);
        int4   rc4 = *(const int4*)(eic + base);
        int4   cc4 = *(const int4*)(eic + NE + base);
        float4 w4  = *(const float4*)(ew + base);

        int rt[4] = {rt4.x, rt4.y, rt4.z, rt4.w};
        int ct[4] = {ct4.x, ct4.y, ct4.z, ct4.w};
        int rc[4] = {rc4.x, rc4.y, rc4.z, rc4.w};
        int cc[4] = {cc4.x, cc4.y, cc4.z, cc4.w};
        float w[4] = {w4.x, w4.y, w4.z, w4.w};

        float dtr[4], dtc[4], dcc[4];
        float4 xd[4];
        #pragma unroll
        for (int k = 0; k < 4; k++) {
            dtr[k] = g_dis_t[rt[k]];
            dtc[k] = g_dis_t[ct[k]];
            dcc[k] = g_dis_c[cc[k]];
            xd[k]  = g_xd4[rc[k]];
        }
        #pragma unroll
        for (int k = 0; k < 4; k++) {
            atomicAdd(&g_coef[ct[k]], dtr[k] * dtc[k]);
            float norm = xd[k].w * w[k] * dcc[k];
            red_add_v4(&g_gc4[cc[k]], norm * xd[k].x, norm * xd[k].y, norm * xd[k].z, 0.f);
        }
    }
    grid_bar(3);

    // ---- phase D: self-loops -> u;  re-zero scratch in place ----
    for (int n = tid; n < NT + NC; n += NTH) {
        float4 u;
        if (n < NT) {
            float d = g_dis_t[n];
            u = make_float4(g_coef[n] + d * d, 1.f, 0.f, 0.f);
            g_dis_t[n] = 0.f;
            g_coef[n] = 0.f;
        } else {
            int c = n - NT;
            float4 gc = g_gc4[c];
            float4 xd = g_xd4[c];
            float d2 = xd.w * xd.w;
            u = make_float4(gc.x + d2 * xd.x,
                            gc.y + d2 * xd.y,
                            gc.z + d2 * xd.z,
                            1.f);
            g_gc4[c] = make_float4(0.f, 0.f, 0.f, 0.f);
            g_dis_c[c] = 0.f;
        }
        g_u[n] = u;
    }
    grid_bar(4);

    // ---- phase E: pair scoring ----
    float blv = bl[0];
    for (int p = tid; p < NP; p += NTH) {
        int s = src[p], d = dst[p];
        float4 us4 = g_u[s], ud4 = g_u[d];
        float us[6] = {0.f, 0.f, 0.f, 0.f, 0.f, 0.f};
        float ud[6] = {0.f, 0.f, 0.f, 0.f, 0.f, 0.f};
        if (s < NT) { us[0] = us4.x; us[1] = us4.y; }
        else        { us[2] = us4.x; us[3] = us4.y; us[4] = us4.z; us[5] = us4.w; }
        if (d < NT) { ud[0] = ud4.x; ud[1] = ud4.y; }
        else        { ud[2] = ud4.x; ud[3] = ud4.y; ud[4] = ud4.z; ud[5] = ud4.w; }
        float acc = blv;
        #pragma unroll
        for (int i = 0; i < 6; i++) {
            float t = 0.f;
            #pragma unroll
            for (int j = 0; j < 6; j++)
                t += sM[6 * i + j] * ud[j];
            acc += us[i] * t;
        }
        out[p] = acc;
    }

    // ---- barrier state reset (last block out resets for next replay) ----
    __syncthreads();
    if (threadIdx.x == 0) {
        __threadfence();
        unsigned prev = atomicAdd(&g_exit, 1u);
        if (prev == GRID - 1) {
            atomicExch(&g_exit, 0u);
            atomicExch(&g_release, 0u);
        }
    }
}

extern "C" void kernel_launch(void* const* d_in, const int* in_sizes, int n_in,
                              void* d_out, int out_size) {
    const float* xcar = (const float*)d_in[0];
    const int*   eit  = (const int*)d_in[1];
    const int*   eic  = (const int*)d_in[2];
    const float* ew   = (const float*)d_in[3];
    const int*   src  = (const int*)d_in[4];
    const int*   dst  = (const int*)d_in[5];
    int w0 = (in_sizes[6] == 1) ? 7 : 6;
    const float* Wt = (const float*)d_in[w0 + 0];
    const float* bt = (const float*)d_in[w0 + 1];
    const float* Wc = (const float*)d_in[w0 + 2];
    const float* bc = (const float*)d_in[w0 + 3];
    const float* wl = (const float*)d_in[w0 + 4];
    const float* bl = (const float*)d_in[w0 + 5];
    float* out = (float*)d_out;

    fused_kernel<<<GRID, TPB>>>(xcar, eit, eic, ew, src, dst,
                                Wt, bt, Wc, bc, wl, bl, out);
}

// round 4
// speedup vs baseline: 1.1561x; 1.1561x over previous
#include <cuda_runtime.h>

#define NT 100000
#define NC 100000
#define NE 1600000
#define NP 200000
#define HD 128

#define GRID 296
#define TPB  512
#define NTH  (GRID * TPB)

// ---- scratch (static __device__, zero-init at load; re-zeroed in phase D) ----
__device__ float  g_dis_t[NT];     // truck deg -> dis_t
__device__ float  g_sum_t[NT];     // unscaled truck sum: sum_r dis_t[rt]
__device__ float  g_deg_c[NC];     // car weighted degree
__device__ float4 g_gc4[NC];       // unscaled car sum: sum_r (dis_c[rc]*w)*x[rc]
__device__ float4 g_xd4[NC];       // packed (x0,x1,x2,dis_c)
__device__ float4 g_u[NT + NC];

// ---- grid barrier state (self-resetting) ----
__device__ unsigned g_count;
__device__ unsigned g_release;
__device__ unsigned g_exit;

__device__ __forceinline__ void grid_bar(unsigned phase) {
    __syncthreads();
    if (threadIdx.x == 0) {
        __threadfence();
        unsigned prev = atomicAdd(&g_count, 1u);
        if (prev == GRID - 1) {
            atomicExch(&g_count, 0u);
            __threadfence();
            atomicExch(&g_release, phase);
        } else {
            while (atomicAdd(&g_release, 0u) < phase) __nanosleep(128);
        }
        __threadfence();   // gpu-scope fence -> CCTL.IVALL: invalidates this SM's L1
    }
    __syncthreads();
}

__device__ __forceinline__ void red_add_v4(float4* addr, float a, float b, float c, float d) {
    asm volatile("red.global.add.v4.f32 [%0], {%1,%2,%3,%4};"
                 :: "l"(addr), "f"(a), "f"(b), "f"(c), "f"(d) : "memory");
}

__global__ void __launch_bounds__(TPB, 2)
fused_kernel(const float* __restrict__ xcar,
             const int* __restrict__ eit,
             const int* __restrict__ eic,
             const float* __restrict__ ew,
             const int* __restrict__ src,
             const int* __restrict__ dst,
             const float* __restrict__ Wt, const float* __restrict__ bt,
             const float* __restrict__ Wc, const float* __restrict__ bc,
             const float* __restrict__ wl, const float* __restrict__ bl,
             float* __restrict__ out) {
    const int tid = blockIdx.x * TPB + threadIdx.x;

    // ---- per-block M = B diag(wl) B^T (6x6) in smem for phase E ----
    __shared__ float sB[6][HD];
    __shared__ float sBw[HD];
    __shared__ float sM[36];
    {
        int h = threadIdx.x;
        if (h < HD) {
            sB[0][h] = Wt[h];
            sB[1][h] = bt[h];
            sB[2][h] = Wc[h];
            sB[3][h] = Wc[HD + h];
            sB[4][h] = Wc[2 * HD + h];
            sB[5][h] = bc[h];
            sBw[h] = wl[h];
        }
        __syncthreads();
        int warp = threadIdx.x >> 5, lane = threadIdx.x & 31;
        if (warp < 4) {
            for (int pi = warp; pi < 36; pi += 4) {
                int i = pi / 6, j = pi % 6;
                float s = 0.f;
                #pragma unroll
                for (int t = lane; t < HD; t += 32)
                    s += sB[i][t] * sB[j][t] * sBw[t];
                #pragma unroll
                for (int o = 16; o > 0; o >>= 1)
                    s += __shfl_xor_sync(0xffffffff, s, o);
                if (lane == 0) sM[pi] = s;
            }
        }
    }

    // ---- phase A: degree accumulation (4 edges/iter, vector loads) ----
    for (int q = tid; q < NE / 4; q += NTH) {
        int base = q * 4;
        int4   ct4 = *(const int4*)(eit + NE + base);
        int4   cc4 = *(const int4*)(eic + NE + base);
        float4 w4  = *(const float4*)(ew + base);
        atomicAdd(&g_dis_t[ct4.x], 1.0f);
        atomicAdd(&g_dis_t[ct4.y], 1.0f);
        atomicAdd(&g_dis_t[ct4.z], 1.0f);
        atomicAdd(&g_dis_t[ct4.w], 1.0f);
        atomicAdd(&g_deg_c[cc4.x], w4.x);
        atomicAdd(&g_deg_c[cc4.y], w4.y);
        atomicAdd(&g_deg_c[cc4.z], w4.z);
        atomicAdd(&g_deg_c[cc4.w], w4.w);
    }
    grid_bar(1);

    // ---- phase B: deg -> dis; pack (x0,x1,x2,dis_c) ----
    for (int i = tid; i < NC; i += NTH) {
        g_dis_t[i] = rsqrtf(g_dis_t[i] + 1.0f);
        float d = rsqrtf(g_deg_c[i] + 1.0f);
        g_deg_c[i] = d;   // now holds dis_c
        g_xd4[i] = make_float4(xcar[3 * i + 0], xcar[3 * i + 1], xcar[3 * i + 2], d);
    }
    grid_bar(2);

    // ---- phase C: edge aggregation, UNSCALED sums (2 random gathers/edge) ----
    for (int q = tid; q < NE / 4; q += NTH) {
        int base = q * 4;
        int4   rt4 = *(const int4*)(eit + base);
        int4   ct4 = *(const int4*)(eit + NE + base);
        int4   rc4 = *(const int4*)(eic + base);
        int4   cc4 = *(const int4*)(eic + NE + base);
        float4 w4  = *(const float4*)(ew + base);

        int rt[4] = {rt4.x, rt4.y, rt4.z, rt4.w};
        int ct[4] = {ct4.x, ct4.y, ct4.z, ct4.w};
        int rc[4] = {rc4.x, rc4.y, rc4.z, rc4.w};
        int cc[4] = {cc4.x, cc4.y, cc4.z, cc4.w};
        float w[4] = {w4.x, w4.y, w4.z, w4.w};

        float dtr[4];
        float4 xd[4];
        #pragma unroll
        for (int k = 0; k < 4; k++) {
            dtr[k] = g_dis_t[rt[k]];
            xd[k]  = g_xd4[rc[k]];
        }
        #pragma unroll
        for (int k = 0; k < 4; k++) {
            atomicAdd(&g_sum_t[ct[k]], dtr[k]);
            float nw = xd[k].w * w[k];   // dis_c[rc] * w  (dest scale applied in phase D)
            red_add_v4(&g_gc4[cc[k]], nw * xd[k].x, nw * xd[k].y, nw * xd[k].z, 0.f);
        }
    }
    grid_bar(3);

    // ---- phase D: apply dest-side scaling + self-loops -> u; re-zero scratch ----
    for (int n = tid; n < NT + NC; n += NTH) {
        float4 u;
        if (n < NT) {
            float d = g_dis_t[n];
            u = make_float4(d * g_sum_t[n] + d * d, 1.f, 0.f, 0.f);
            g_dis_t[n] = 0.f;
            g_sum_t[n] = 0.f;
        } else {
            int c = n - NT;
            float4 gc = g_gc4[c];
            float4 xd = g_xd4[c];
            float d  = xd.w;
            float d2 = d * d;
            u = make_float4(d * gc.x + d2 * xd.x,
                            d * gc.y + d2 * xd.y,
                            d * gc.z + d2 * xd.z,
                            1.f);
            g_gc4[c] = make_float4(0.f, 0.f, 0.f, 0.f);
            g_deg_c[c] = 0.f;
        }
        g_u[n] = u;
    }
    grid_bar(4);

    // ---- phase E: pair scoring ----
    float blv = bl[0];
    for (int p = tid; p < NP; p += NTH) {
        int s = src[p], d = dst[p];
        float4 us4 = g_u[s], ud4 = g_u[d];
        float us[6] = {0.f, 0.f, 0.f, 0.f, 0.f, 0.f};
        float ud[6] = {0.f, 0.f, 0.f, 0.f, 0.f, 0.f};
        if (s < NT) { us[0] = us4.x; us[1] = us4.y; }
        else        { us[2] = us4.x; us[3] = us4.y; us[4] = us4.z; us[5] = us4.w; }
        if (d < NT) { ud[0] = ud4.x; ud[1] = ud4.y; }
        else        { ud[2] = ud4.x; ud[3] = ud4.y; ud[4] = ud4.z; ud[5] = ud4.w; }
        float acc = blv;
        #pragma unroll
        for (int i = 0; i < 6; i++) {
            float t = 0.f;
            #pragma unroll
            for (int j = 0; j < 6; j++)
                t += sM[6 * i + j] * ud[j];
            acc += us[i] * t;
        }
        out[p] = acc;
    }

    // ---- barrier state reset for next graph replay ----
    __syncthreads();
    if (threadIdx.x == 0) {
        __threadfence();
        unsigned prev = atomicAdd(&g_exit, 1u);
        if (prev == GRID - 1) {
            atomicExch(&g_exit, 0u);
            atomicExch(&g_release, 0u);
        }
    }
}

extern "C" void kernel_launch(void* const* d_in, const int* in_sizes, int n_in,
                              void* d_out, int out_size) {
    const float* xcar = (const float*)d_in[0];
    const int*   eit  = (const int*)d_in[1];
    const int*   eic  = (const int*)d_in[2];
    const float* ew   = (const float*)d_in[3];
    const int*   src  = (const int*)d_in[4];
    const int*   dst  = (const int*)d_in[5];
    int w0 = (in_sizes[6] == 1) ? 7 : 6;
    const float* Wt = (const float*)d_in[w0 + 0];
    const float* bt = (const float*)d_in[w0 + 1];
    const float* Wc = (const float*)d_in[w0 + 2];
    const float* bc = (const float*)d_in[w0 + 3];
    const float* wl = (const float*)d_in[w0 + 4];
    const float* bl = (const float*)d_in[w0 + 5];
    float* out = (float*)d_out;

    fused_kernel<<<GRID, TPB>>>(xcar, eit, eic, ew, src, dst,
                                Wt, bt, Wc, bc, wl, bl, out);
}

// round 5
// speedup vs baseline: 1.4933x; 1.2917x over previous
#include <cuda_runtime.h>

#define NT 100000
#define NC 100000
#define NE 1600000
#define NP 200000
#define HD 128

// ---- scratch (static __device__) ----
__device__ float  g_dis_t[NT];     // truck deg -> dis_t
__device__ float  g_sum_t[NT];     // unscaled truck sum: sum_r dis_t[rt]
__device__ float  g_deg_c[NC];     // car weighted degree -> dis_c
__device__ float4 g_gc4[NC];       // unscaled car sum
__device__ float4 g_xd4[NC];       // packed (x0,x1,x2,dis_c)
__device__ float4 g_u[NT + NC];    // per-node compact coefficients
__device__ float  g_M[36];         // 6x6 quadratic-form matrix

__device__ __forceinline__ void red_add_v4(float4* addr, float a, float b, float c, float d) {
    asm volatile("red.global.add.v4.f32 [%0], {%1,%2,%3,%4};"
                 :: "l"(addr), "f"(a), "f"(b), "f"(c), "f"(d) : "memory");
}

// ---- k0: zero accumulators (dis_t, sum_t, deg_c, gc4) ----
__global__ void k_zero() {
    int i = blockIdx.x * blockDim.x + threadIdx.x;
    if (i < NT) { g_dis_t[i] = 0.f; g_sum_t[i] = 0.f; }
    if (i < NC) { g_deg_c[i] = 0.f; g_gc4[i] = make_float4(0.f, 0.f, 0.f, 0.f); }
}

// ---- kM: 6x6 quadratic form M[i][j] = sum_h B_i[h] B_j[h] wlin[h] ----
__global__ void k_M(const float* __restrict__ Wt, const float* __restrict__ bt,
                    const float* __restrict__ Wc, const float* __restrict__ bc,
                    const float* __restrict__ wl) {
    __shared__ float B[6][HD];
    __shared__ float Bw[HD];
    int h = threadIdx.x;  // 128 threads
    B[0][h] = Wt[h];
    B[1][h] = bt[h];
    B[2][h] = Wc[h];
    B[3][h] = Wc[HD + h];
    B[4][h] = Wc[2 * HD + h];
    B[5][h] = bc[h];
    Bw[h] = wl[h];
    __syncthreads();
    int warp = h >> 5, lane = h & 31;
    for (int pi = warp; pi < 36; pi += 4) {
        int i = pi / 6, j = pi % 6;
        float s = 0.f;
        #pragma unroll
        for (int t = lane; t < HD; t += 32)
            s += B[i][t] * B[j][t] * Bw[t];
        #pragma unroll
        for (int o = 16; o > 0; o >>= 1)
            s += __shfl_xor_sync(0xffffffff, s, o);
        if (lane == 0) g_M[pi] = s;
    }
}

// ---- k1: degree accumulation (both graphs), 4 edges/thread ----
__global__ void __launch_bounds__(256) k_deg(const int* __restrict__ eit,
                                             const int* __restrict__ eic,
                                             const float* __restrict__ ew) {
    int t = blockIdx.x * blockDim.x + threadIdx.x;
    int base = t * 4;
    if (base >= NE) return;
    int4   ct4 = *(const int4*)(eit + NE + base);
    int4   cc4 = *(const int4*)(eic + NE + base);
    float4 w4  = *(const float4*)(ew + base);
    atomicAdd(&g_dis_t[ct4.x], 1.0f);
    atomicAdd(&g_dis_t[ct4.y], 1.0f);
    atomicAdd(&g_dis_t[ct4.z], 1.0f);
    atomicAdd(&g_dis_t[ct4.w], 1.0f);
    atomicAdd(&g_deg_c[cc4.x], w4.x);
    atomicAdd(&g_deg_c[cc4.y], w4.y);
    atomicAdd(&g_deg_c[cc4.z], w4.z);
    atomicAdd(&g_deg_c[cc4.w], w4.w);
}

// ---- k2: deg -> dis; pack (x0,x1,x2,dis_c) ----
__global__ void k_dis(const float* __restrict__ xcar) {
    int i = blockIdx.x * blockDim.x + threadIdx.x;
    if (i >= NC) return;
    g_dis_t[i] = rsqrtf(g_dis_t[i] + 1.0f);
    float d = rsqrtf(g_deg_c[i] + 1.0f);
    g_xd4[i] = make_float4(xcar[3 * i + 0], xcar[3 * i + 1], xcar[3 * i + 2], d);
}

// ---- k3: edge aggregation, UNSCALED sums (2 random gathers/edge) ----
__global__ void __launch_bounds__(256) k_agg(const int* __restrict__ eit,
                                             const int* __restrict__ eic,
                                             const float* __restrict__ ew) {
    int t = blockIdx.x * blockDim.x + threadIdx.x;
    int base = t * 4;
    if (base >= NE) return;
    int4   rt4 = *(const int4*)(eit + base);
    int4   ct4 = *(const int4*)(eit + NE + base);
    int4   rc4 = *(const int4*)(eic + base);
    int4   cc4 = *(const int4*)(eic + NE + base);
    float4 w4  = *(const float4*)(ew + base);

    int rt[4] = {rt4.x, rt4.y, rt4.z, rt4.w};
    int ct[4] = {ct4.x, ct4.y, ct4.z, ct4.w};
    int rc[4] = {rc4.x, rc4.y, rc4.z, rc4.w};
    int cc[4] = {cc4.x, cc4.y, cc4.z, cc4.w};
    float w[4] = {w4.x, w4.y, w4.z, w4.w};

    // front-batch random gathers for MLP
    float dtr[4];
    float4 xd[4];
    #pragma unroll
    for (int k = 0; k < 4; k++) {
        dtr[k] = g_dis_t[rt[k]];
        xd[k]  = g_xd4[rc[k]];
    }
    #pragma unroll
    for (int k = 0; k < 4; k++) {
        atomicAdd(&g_sum_t[ct[k]], dtr[k]);
        float nw = xd[k].w * w[k];   // dis_c[rc]*w; dest scale applied in k_u
        red_add_v4(&g_gc4[cc[k]], nw * xd[k].x, nw * xd[k].y, nw * xd[k].z, 0.f);
    }
}

// ---- k4: dest-side scaling + self-loops -> u ----
__global__ void k_u() {
    int n = blockIdx.x * blockDim.x + threadIdx.x;
    if (n >= NT + NC) return;
    float4 u;
    if (n < NT) {
        float d = g_dis_t[n];
        u = make_float4(d * g_sum_t[n] + d * d, 1.f, 0.f, 0.f);
    } else {
        int c = n - NT;
        float4 gc = g_gc4[c];
        float4 xd = g_xd4[c];
        float d  = xd.w;
        float d2 = d * d;
        u = make_float4(d * gc.x + d2 * xd.x,
                        d * gc.y + d2 * xd.y,
                        d * gc.z + d2 * xd.z,
                        1.f);
    }
    g_u[n] = u;
}

// ---- k5: pair scoring, 2 pairs/thread ----
__global__ void __launch_bounds__(256) k_pair(const int* __restrict__ src,
                                              const int* __restrict__ dst,
                                              const float* __restrict__ bl,
                                              float* __restrict__ out) {
    __shared__ float M[36];
    if (threadIdx.x < 36) M[threadIdx.x] = g_M[threadIdx.x];
    __syncthreads();
    int t = blockIdx.x * blockDim.x + threadIdx.x;
    int base = t * 2;
    if (base >= NP) return;
    int2 s2 = *(const int2*)(src + base);
    int2 d2 = *(const int2*)(dst + base);
    float blv = bl[0];
    int ss[2] = {s2.x, s2.y};
    int dd[2] = {d2.x, d2.y};
    float4 usv[2], udv[2];
    #pragma unroll
    for (int k = 0; k < 2; k++) { usv[k] = g_u[ss[k]]; udv[k] = g_u[dd[k]]; }
    float res[2];
    #pragma unroll
    for (int k = 0; k < 2; k++) {
        float us[6] = {0.f, 0.f, 0.f, 0.f, 0.f, 0.f};
        float ud[6] = {0.f, 0.f, 0.f, 0.f, 0.f, 0.f};
        if (ss[k] < NT) { us[0] = usv[k].x; us[1] = usv[k].y; }
        else            { us[2] = usv[k].x; us[3] = usv[k].y; us[4] = usv[k].z; us[5] = usv[k].w; }
        if (dd[k] < NT) { ud[0] = udv[k].x; ud[1] = udv[k].y; }
        else            { ud[2] = udv[k].x; ud[3] = udv[k].y; ud[4] = udv[k].z; ud[5] = udv[k].w; }
        float acc = blv;
        #pragma unroll
        for (int i = 0; i < 6; i++) {
            float tt = 0.f;
            #pragma unroll
            for (int j = 0; j < 6; j++)
                tt += M[6 * i + j] * ud[j];
            acc += us[i] * tt;
        }
        res[k] = acc;
    }
    out[base] = res[0];
    if (base + 1 < NP) out[base + 1] = res[1];
}

extern "C" void kernel_launch(void* const* d_in, const int* in_sizes, int n_in,
                              void* d_out, int out_size) {
    const float* xcar = (const float*)d_in[0];
    const int*   eit  = (const int*)d_in[1];
    const int*   eic  = (const int*)d_in[2];
    const float* ew   = (const float*)d_in[3];
    const int*   src  = (const int*)d_in[4];
    const int*   dst  = (const int*)d_in[5];
    int w0 = (in_sizes[6] == 1) ? 7 : 6;
    const float* Wt = (const float*)d_in[w0 + 0];
    const float* bt = (const float*)d_in[w0 + 1];
    const float* Wc = (const float*)d_in[w0 + 2];
    const float* bc = (const float*)d_in[w0 + 3];
    const float* wl = (const float*)d_in[w0 + 4];
    const float* bl = (const float*)d_in[w0 + 5];
    float* out = (float*)d_out;

    const int TPB = 256;
    k_zero<<<(NC + TPB - 1) / TPB, TPB>>>();
    k_M<<<1, HD>>>(Wt, bt, Wc, bc, wl);
    k_deg<<<(NE / 4 + TPB - 1) / TPB, TPB>>>(eit, eic, ew);
    k_dis<<<(NC + TPB - 1) / TPB, TPB>>>(xcar);
    k_agg<<<(NE / 4 + TPB - 1) / TPB, TPB>>>(eit, eic, ew);
    k_u<<<(NT + NC + TPB - 1) / TPB, TPB>>>();
    k_pair<<<(NP / 2 + TPB - 1) / TPB, TPB>>>(src, dst, bl, out);
}